// round 2
// baseline (speedup 1.0000x reference)
#include <cuda_runtime.h>

#define H 128
#define B 1024
#define K 10
#define NSAMP (B + B * K)   // 11264
#define MARGIN 1.0f

// Scratch for per-sample scores: [0,B) = positive, [B, NSAMP) = negatives.
__device__ float g_scores[NSAMP];

// One CTA of 128 threads per sample.
// score = h^T R t = sum_j ( sum_i h[i] * R[i*H + j] ) * t[j]
// Thread j owns column j -> per i-iteration the CTA reads 128 consecutive
// floats of R (coalesced 512B); h[i] is a shared-memory broadcast.
__global__ void __launch_bounds__(H) rescal_score_kernel(
    const float* __restrict__ ent,
    const float* __restrict__ rel,
    const int* __restrict__ pos_h, const int* __restrict__ pos_t, const int* __restrict__ pos_r,
    const int* __restrict__ neg_h, const int* __restrict__ neg_t, const int* __restrict__ neg_r)
{
    const int s = blockIdx.x;
    int hi, ti, ri;
    if (s < B) {
        hi = pos_h[s]; ti = pos_t[s]; ri = pos_r[s];
    } else {
        const int n = s - B;
        hi = neg_h[n]; ti = neg_t[n]; ri = neg_r[n];
    }

    __shared__ float h_sh[H];
    __shared__ float t_sh[H];
    const int j = threadIdx.x;

    h_sh[j] = ent[(long long)hi * H + j];
    t_sh[j] = ent[(long long)ti * H + j];
    __syncthreads();

    const float* __restrict__ R = rel + (long long)ri * (H * H);

    float acc = 0.0f;
#pragma unroll 8
    for (int i = 0; i < H; ++i) {
        acc += h_sh[i] * __ldg(R + i * H + j);
    }
    float v = acc * t_sh[j];

    // Reduce 128 values -> 1.
#pragma unroll
    for (int off = 16; off > 0; off >>= 1)
        v += __shfl_down_sync(0xffffffffu, v, off);

    __shared__ float warp_sums[4];
    if ((j & 31) == 0) warp_sums[j >> 5] = v;
    __syncthreads();
    if (j == 0) {
        g_scores[s] = warp_sums[0] + warp_sums[1] + warp_sums[2] + warp_sums[3];
    }
}

// Single block of 1024 threads: thread b handles one positive.
__global__ void __launch_bounds__(B) rescal_loss_kernel(float* __restrict__ out)
{
    const int b = threadIdx.x;
    const float p = g_scores[b];
    float n = 0.0f;
#pragma unroll
    for (int k = 0; k < K; ++k)
        n += g_scores[B + b * K + k];
    n *= (1.0f / (float)K);

    float l = fmaxf(n - p + MARGIN, 0.0f);

    // Block reduce 1024 -> 1.
#pragma unroll
    for (int off = 16; off > 0; off >>= 1)
        l += __shfl_down_sync(0xffffffffu, l, off);

    __shared__ float ws[32];
    if ((b & 31) == 0) ws[b >> 5] = l;
    __syncthreads();
    if (b < 32) {
        float v = ws[b];
#pragma unroll
        for (int off = 16; off > 0; off >>= 1)
            v += __shfl_down_sync(0xffffffffu, v, off);
        if (b == 0) out[0] = v;
    }
}

extern "C" void kernel_launch(void* const* d_in, const int* in_sizes, int n_in,
                              void* d_out, int out_size)
{
    const float* ent   = (const float*)d_in[0];
    const float* rel   = (const float*)d_in[1];
    const int*   pos_h = (const int*)d_in[2];
    const int*   pos_t = (const int*)d_in[3];
    const int*   pos_r = (const int*)d_in[4];
    const int*   neg_h = (const int*)d_in[5];
    const int*   neg_t = (const int*)d_in[6];
    const int*   neg_r = (const int*)d_in[7];
    float* out = (float*)d_out;

    rescal_score_kernel<<<NSAMP, H>>>(ent, rel, pos_h, pos_t, pos_r,
                                      neg_h, neg_t, neg_r);
    rescal_loss_kernel<<<1, B>>>(out);
}

// round 4
// speedup vs baseline: 1.0087x; 1.0087x over previous
#include <cuda_runtime.h>

#define H 128
#define B 1024
#define K 10
#define NSAMP (B + B * K)   // 11264
#define REL 1000
#define MARGIN 1.0f
#define CHUNK 16            // samples per CTA pass (4 per warp)

// ---------------- global scratch ----------------
__device__ int   g_bin_start[REL + 1];
__device__ int   g_cursor[REL];
__device__ int   g_sorted_sid[NSAMP];   // original sample id, sorted by relation
__device__ int   g_sorted_h[NSAMP];     // head entity idx, sorted by relation
__device__ int   g_sorted_t[NSAMP];     // tail entity idx, sorted by relation
__device__ float g_scores[NSAMP];       // scores in ORIGINAL sample order

// ---------------- kernel 1: histogram + exclusive scan (1 block) ----------------
__global__ void __launch_bounds__(1024) hist_scan_kernel(
    const int* __restrict__ pos_r, const int* __restrict__ neg_r)
{
    __shared__ int hist[1024];
    __shared__ int cnt_save[1024];
    const int t = threadIdx.x;
    hist[t] = 0;
    __syncthreads();

    for (int s = t; s < NSAMP; s += 1024) {
        int r = (s < B) ? pos_r[s] : neg_r[s - B];
        atomicAdd(&hist[r], 1);
    }
    __syncthreads();
    cnt_save[t] = hist[t];
    __syncthreads();

    // Hillis-Steele inclusive scan over 1024 entries
#pragma unroll
    for (int off = 1; off < 1024; off <<= 1) {
        int u = (t >= off) ? hist[t - off] : 0;
        __syncthreads();
        if (t >= off) hist[t] += u;
        __syncthreads();
    }

    if (t < REL) {
        int excl = hist[t] - cnt_save[t];
        g_bin_start[t] = excl;
        g_cursor[t]    = excl;
    }
    if (t == REL - 1) g_bin_start[REL] = hist[REL - 1];
}

// ---------------- kernel 2: scatter samples into bins ----------------
__global__ void scatter_kernel(
    const int* __restrict__ pos_h, const int* __restrict__ pos_t, const int* __restrict__ pos_r,
    const int* __restrict__ neg_h, const int* __restrict__ neg_t, const int* __restrict__ neg_r)
{
    int s = blockIdx.x * blockDim.x + threadIdx.x;
    if (s >= NSAMP) return;
    int r, hi, ti;
    if (s < B) { r = pos_r[s]; hi = pos_h[s]; ti = pos_t[s]; }
    else       { int n = s - B; r = neg_r[n]; hi = neg_h[n]; ti = neg_t[n]; }
    int pos = atomicAdd(&g_cursor[r], 1);
    g_sorted_sid[pos] = s;
    g_sorted_h[pos]   = hi;
    g_sorted_t[pos]   = ti;
}

// ---------------- kernel 3: grouped scoring, 1 CTA per relation ----------------
// dynamic smem: R [128*128] + h [16*128] + t [16*128] floats = 81920 bytes
#define SCORE_SMEM ((H * H + 2 * CHUNK * H) * (int)sizeof(float))

__global__ void __launch_bounds__(H) score_grouped_kernel(
    const float* __restrict__ ent,
    const float* __restrict__ rel)
{
    extern __shared__ float sm[];
    float*  Rsh = sm;                       // 16384 floats
    float*  hsh = sm + H * H;               // 2048 floats
    float*  tsh = hsh + CHUNK * H;          // 2048 floats
    __shared__ int ssid[CHUNK];
    __shared__ int shix[CHUNK];
    __shared__ int stix[CHUNK];

    const int r   = blockIdx.x;
    const int beg = g_bin_start[r];
    const int m   = g_bin_start[r + 1] - beg;
    if (m == 0) return;

    const int tid  = threadIdx.x;
    const int lane = tid & 31;
    const int w    = tid >> 5;

    // Load R (64 KB) into smem, coalesced float4.
    const float4* Rg = (const float4*)(rel + (size_t)r * (H * H));
    float4* R4 = (float4*)Rsh;
#pragma unroll
    for (int k = 0; k < (H * H) / 4 / H; ++k)       // 32 iters
        R4[k * H + tid] = Rg[k * H + tid];

    for (int base = 0; base < m; base += CHUNK) {
        __syncthreads();   // previous pass done with staging (also covers R load on iter 0)

        if (tid < CHUNK) {
            int idx = base + tid;
            if (idx < m) {
                ssid[tid] = g_sorted_sid[beg + idx];
                shix[tid] = g_sorted_h[beg + idx];
                stix[tid] = g_sorted_t[beg + idx];
            } else {
                ssid[tid] = -1; shix[tid] = -1; stix[tid] = -1;
            }
        }
        __syncthreads();

        // stage h, t vectors (coalesced; zero for padding samples)
#pragma unroll
        for (int s16 = 0; s16 < CHUNK; ++s16) {
            int hi = shix[s16], ti = stix[s16];
            hsh[s16 * H + tid] = (hi >= 0) ? ent[(size_t)hi * H + tid] : 0.0f;
            tsh[s16 * H + tid] = (ti >= 0) ? ent[(size_t)ti * H + tid] : 0.0f;
        }
        __syncthreads();

        // Each warp handles 4 samples; each thread owns 4 consecutive columns.
        const float* hb = hsh + (w * 4) * H;
        float4 a0 = make_float4(0.f, 0.f, 0.f, 0.f);
        float4 a1 = a0, a2 = a0, a3 = a0;

#pragma unroll 8
        for (int i = 0; i < H; ++i) {
            float4 rv = R4[i * 32 + lane];
            float b0 = hb[i];
            float b1 = hb[H + i];
            float b2 = hb[2 * H + i];
            float b3 = hb[3 * H + i];
            a0.x += rv.x * b0; a0.y += rv.y * b0; a0.z += rv.z * b0; a0.w += rv.w * b0;
            a1.x += rv.x * b1; a1.y += rv.y * b1; a1.z += rv.z * b1; a1.w += rv.w * b1;
            a2.x += rv.x * b2; a2.y += rv.y * b2; a2.z += rv.z * b2; a2.w += rv.w * b2;
            a3.x += rv.x * b3; a3.y += rv.y * b3; a3.z += rv.z * b3; a3.w += rv.w * b3;
        }

        // epilogue: dot with t, warp-reduce, write score
#pragma unroll
        for (int s = 0; s < 4; ++s) {
            float4 a = (s == 0) ? a0 : (s == 1) ? a1 : (s == 2) ? a2 : a3;
            const float4 tv = ((const float4*)(tsh + (w * 4 + s) * H))[lane];
            float v = a.x * tv.x + a.y * tv.y + a.z * tv.z + a.w * tv.w;
#pragma unroll
            for (int off = 16; off > 0; off >>= 1)
                v += __shfl_down_sync(0xffffffffu, v, off);
            int sid = ssid[w * 4 + s];
            if (lane == 0 && sid >= 0) g_scores[sid] = v;
        }
    }
}

// ---------------- kernel 4: hinge loss reduction ----------------
__global__ void __launch_bounds__(B) rescal_loss_kernel(float* __restrict__ out)
{
    const int b = threadIdx.x;
    const float p = g_scores[b];
    float n = 0.0f;
#pragma unroll
    for (int k = 0; k < K; ++k)
        n += g_scores[B + b * K + k];
    n *= (1.0f / (float)K);

    float l = fmaxf(n - p + MARGIN, 0.0f);

#pragma unroll
    for (int off = 16; off > 0; off >>= 1)
        l += __shfl_down_sync(0xffffffffu, l, off);

    __shared__ float ws[32];
    if ((b & 31) == 0) ws[b >> 5] = l;
    __syncthreads();
    if (b < 32) {
        float v = ws[b];
#pragma unroll
        for (int off = 16; off > 0; off >>= 1)
            v += __shfl_down_sync(0xffffffffu, v, off);
        if (b == 0) out[0] = v;
    }
}

// ---------------- launcher ----------------
extern "C" void kernel_launch(void* const* d_in, const int* in_sizes, int n_in,
                              void* d_out, int out_size)
{
    const float* ent   = (const float*)d_in[0];
    const float* rel   = (const float*)d_in[1];
    const int*   pos_h = (const int*)d_in[2];
    const int*   pos_t = (const int*)d_in[3];
    const int*   pos_r = (const int*)d_in[4];
    const int*   neg_h = (const int*)d_in[5];
    const int*   neg_t = (const int*)d_in[6];
    const int*   neg_r = (const int*)d_in[7];
    float* out = (float*)d_out;

    cudaFuncSetAttribute(score_grouped_kernel,
                         cudaFuncAttributeMaxDynamicSharedMemorySize, SCORE_SMEM);

    hist_scan_kernel<<<1, 1024>>>(pos_r, neg_r);
    scatter_kernel<<<(NSAMP + 255) / 256, 256>>>(pos_h, pos_t, pos_r,
                                                 neg_h, neg_t, neg_r);
    score_grouped_kernel<<<REL, H, SCORE_SMEM>>>(ent, rel);
    rescal_loss_kernel<<<1, B>>>(out);
}